// round 8
// baseline (speedup 1.0000x reference)
#include <cuda_runtime.h>
#include <cuda_fp16.h>
#include <math.h>
#include <stdint.h>

#define SQ   2048
#define DIM  1024
#define NH   16
#define HDK  64
#define MLPD 4096
#define QKVN 3072

// ---------------- scratch (no allocations allowed) ----------------
__device__ unsigned short g_h   [SQ*DIM];     // fp16 LN out
__device__ unsigned short g_qkv [SQ*QKVN];    // fp16 q,k,v
__device__ unsigned short g_ao  [SQ*DIM];     // fp16 attention out [H,S,DK]
__device__ float          g_x1  [SQ*DIM];
__device__ unsigned short g_f   [SQ*MLPD];    // fp16 gelu out
__device__ unsigned short g_wqkv[QKVN*DIM];   // fp16 weights, [N,K]
__device__ unsigned short g_wo  [DIM*DIM];
__device__ unsigned short g_w1  [MLPD*DIM];
__device__ unsigned short g_w2  [DIM*MLPD];
__device__ float          g_bqkv[QKVN];

// ---------------- helpers ----------------
__device__ __forceinline__ uint32_t smem_u32(const void* p) {
    uint32_t a;
    asm("{ .reg .u64 t; cvta.to.shared.u64 t, %1; cvt.u32.u64 %0, t; }" : "=r"(a) : "l"(p));
    return a;
}

__device__ __forceinline__ void cp_async16(uint32_t sdst, const void* gsrc) {
    asm volatile("cp.async.cg.shared.global [%0], [%1], 16;" :: "r"(sdst), "l"(gsrc) : "memory");
}
#define CP_COMMIT() asm volatile("cp.async.commit_group;" ::: "memory")
#define CP_WAIT(n)  asm volatile("cp.async.wait_group %0;" :: "n"(n) : "memory")

#define LDSM4(r, addr) \
    asm volatile("ldmatrix.sync.aligned.m8n8.x4.shared.b16 {%0,%1,%2,%3}, [%4];" \
        : "=r"((r)[0]), "=r"((r)[1]), "=r"((r)[2]), "=r"((r)[3]) : "r"(addr))

#define LDSM4T(r, addr) \
    asm volatile("ldmatrix.sync.aligned.m8n8.x4.trans.shared.b16 {%0,%1,%2,%3}, [%4];" \
        : "=r"((r)[0]), "=r"((r)[1]), "=r"((r)[2]), "=r"((r)[3]) : "r"(addr))

#define MMA_F16(c, a, b0, b1) \
    asm volatile("mma.sync.aligned.m16n8k16.row.col.f32.f16.f16.f32 " \
        "{%0,%1,%2,%3}, {%4,%5,%6,%7}, {%8,%9}, {%0,%1,%2,%3};" \
        : "+f"((c)[0]), "+f"((c)[1]), "+f"((c)[2]), "+f"((c)[3]) \
        : "r"((a)[0]), "r"((a)[1]), "r"((a)[2]), "r"((a)[3]), "r"(b0), "r"(b1))

#define MMA_F16R(c, a0, a1, a2, a3, b0, b1) \
    asm volatile("mma.sync.aligned.m16n8k16.row.col.f32.f16.f16.f32 " \
        "{%0,%1,%2,%3}, {%4,%5,%6,%7}, {%8,%9}, {%0,%1,%2,%3};" \
        : "+f"((c)[0]), "+f"((c)[1]), "+f"((c)[2]), "+f"((c)[3]) \
        : "r"(a0), "r"(a1), "r"(a2), "r"(a3), "r"(b0), "r"(b1))

__device__ __forceinline__ unsigned short f2h(float v) {
    return __half_as_ushort(__float2half_rn(v));
}
__device__ __forceinline__ uint32_t pack2_h(float a, float b) {
    __half2 h = __floats2half2_rn(a, b);
    return *(uint32_t*)&h;
}

// ---------------- layernorm -> fp16 ----------------
__device__ __forceinline__ float block_sum_256(float v, float* sh) {
    int lane = threadIdx.x & 31, w = threadIdx.x >> 5;
    #pragma unroll
    for (int o = 16; o; o >>= 1) v += __shfl_xor_sync(0xffffffffu, v, o);
    __syncthreads();
    if (lane == 0) sh[w] = v;
    __syncthreads();
    float r = 0.f;
    #pragma unroll
    for (int i = 0; i < 8; i++) r += sh[i];
    return r;
}

__global__ void ln_h_kernel(const float* __restrict__ x, const float* __restrict__ g,
                            const float* __restrict__ b, unsigned short* __restrict__ oh) {
    __shared__ float sh[8];
    int row = blockIdx.x;
    const float* xr = x + (size_t)row * DIM;
    int t = threadIdx.x;
    float v0[4];
    float s = 0.f;
    #pragma unroll
    for (int u = 0; u < 4; u++) { v0[u] = xr[t + u * 256]; s += v0[u]; }
    s = block_sum_256(s, sh);
    float mean = s * (1.0f / DIM);
    float vs = 0.f;
    #pragma unroll
    for (int u = 0; u < 4; u++) { float d = v0[u] - mean; vs += d * d; }
    vs = block_sum_256(vs, sh);
    float rstd = rsqrtf(vs * (1.0f / DIM) + 1e-5f);
    #pragma unroll
    for (int u = 0; u < 4; u++) {
        int c = t + u * 256;
        oh[(size_t)row * DIM + c] = f2h((v0[u] - mean) * rstd * g[c] + b[c]);
    }
}

// ---------------- merged weight prep: all transposes + bias concat ----------------
// block layout (32,8). Matrices transposed in 32x32 tiles.
// blocks [0,1024) wq | [1024,2048) wk | [2048,3072) wv | [3072,4096) wo
// [4096,8192) w1 (R=1024,C=4096) | [8192,12288) w2 (R=4096,C=1024) | [12288,12300) bias
__global__ void prep_kernel(const float* __restrict__ wq, const float* __restrict__ wk,
                            const float* __restrict__ wv, const float* __restrict__ wo,
                            const float* __restrict__ w1, const float* __restrict__ w2,
                            const float* __restrict__ bq, const float* __restrict__ bk,
                            const float* __restrict__ bv,
                            unsigned short* __restrict__ owqkv, unsigned short* __restrict__ owo,
                            unsigned short* __restrict__ ow1, unsigned short* __restrict__ ow2,
                            float* __restrict__ obqkv) {
    int bid = blockIdx.x;
    if (bid >= 12288) {
        int i = (bid - 12288) * 256 + threadIdx.y * 32 + threadIdx.x;
        if (i < DIM) obqkv[i] = bq[i];
        else if (i < 2 * DIM) obqkv[i] = bk[i - DIM];
        else obqkv[i] = bv[i - 2 * DIM];
        return;
    }
    const float* in;
    unsigned short* out;
    int R, C, l;
    if (bid < 4096) {
        l = bid & 1023;
        R = DIM; C = DIM;
        int m = bid >> 10;
        in  = (m == 0) ? wq : (m == 1) ? wk : (m == 2) ? wv : wo;
        out = (m == 3) ? owo : owqkv + (size_t)m * DIM * DIM;
    } else if (bid < 8192) {
        l = bid - 4096; R = DIM; C = MLPD; in = w1; out = ow1;
    } else {
        l = bid - 8192; R = MLPD; C = DIM; in = w2; out = ow2;
    }
    int nbx = C >> 5;
    int bx = l % nbx, by = l / nbx;
    __shared__ float t[32][33];
    int c0 = bx * 32, r0 = by * 32;
    #pragma unroll
    for (int u = 0; u < 4; u++) {
        int r = r0 + threadIdx.y + u * 8;
        t[threadIdx.y + u * 8][threadIdx.x] = in[(size_t)r * C + c0 + threadIdx.x];
    }
    __syncthreads();
    #pragma unroll
    for (int u = 0; u < 4; u++) {
        int c = c0 + threadIdx.y + u * 8;
        out[(size_t)c * R + r0 + threadIdx.x] = f2h(t[threadIdx.x][threadIdx.y + u * 8]);
    }
}

// ---------------- fp16 GEMM: C = A_f16 @ B_f16^T, single-barrier multistage ----------------
#define TILEB 10240u
#define STAGES 4
#define GEMM_SMEM (STAGES * 2 * 10240)

__global__ __launch_bounds__(256, 2)
void gemm_mma_kernel(const unsigned short* __restrict__ A, const unsigned short* __restrict__ B,
                     const float* __restrict__ bias, const float* __restrict__ res,
                     float* __restrict__ outF, unsigned short* __restrict__ outH,
                     int N, int K, int gelu) {
    extern __shared__ char smem[];
    const uint32_t sb = smem_u32(smem);
    const int tid  = threadIdx.x;
    const int wid  = tid >> 5;
    const int lane = tid & 31;
    const int wm = wid >> 2;
    const int wn = wid & 3;
    const int bm = blockIdx.y * 128;
    const int bn = blockIdx.x * 128;
    const int g  = lane >> 2;
    const int t4 = lane & 3;

    const uint32_t aOff = (uint32_t)((((lane >> 3) & 1) * 8 + (lane & 7)) * 80 + (lane >> 4) * 16);
    const uint32_t bOff = (uint32_t)(((lane >> 4) * 8 + (lane & 7)) * 80 + ((lane >> 3) & 1) * 16);

    float acc[4][4][4];
    #pragma unroll
    for (int i = 0; i < 4; i++)
        #pragma unroll
        for (int j = 0; j < 4; j++)
            #pragma unroll
            for (int q = 0; q < 4; q++) acc[i][j][q] = 0.f;

    const int NCH = K >> 5;
    const unsigned short* gsrc[2] = {A, B};
    const int rbase[2] = {bm, bn};

    auto load_chunk = [&](int stage, int k0) {
        #pragma unroll
        for (int t = 0; t < 2; t++) {
            uint32_t dst = sb + (uint32_t)(stage * 2 + t) * TILEB;
            const unsigned short* gp = gsrc[t];
            #pragma unroll
            for (int u = 0; u < 2; u++) {
                int idx = tid + 256 * u;
                int r = idx >> 2;
                int cc = idx & 3;
                cp_async16(dst + (uint32_t)(r * 80 + cc * 16),
                           gp + (size_t)(rbase[t] + r) * K + k0 + cc * 8);
            }
        }
        CP_COMMIT();
    };

    // prologue: S-1 chunks
    #pragma unroll
    for (int s = 0; s < STAGES - 1; s++) load_chunk(s, s * 32);

    int st = 0;
    for (int i = 0; i < NCH; i++) {
        CP_WAIT(STAGES - 2);
        __syncthreads();
        // prefetch chunk i+S-1 into the stage freed at iter i-1
        if (i + STAGES - 1 < NCH) load_chunk((st + STAGES - 1) & (STAGES - 1), (i + STAGES - 1) * 32);
        else                      CP_COMMIT();

        const uint32_t aB = sb + (uint32_t)(st * 2) * TILEB;
        const uint32_t bB = aB + TILEB;

        #pragma unroll
        for (int ks = 0; ks < 2; ks++) {
            uint32_t bf[2][4];
            #pragma unroll
            for (int np = 0; np < 2; np++) {
                uint32_t o = (uint32_t)((wn * 32 + np * 16) * 80 + ks * 32) + bOff;
                LDSM4(bf[np], bB + o);
            }
            #pragma unroll
            for (int mt = 0; mt < 4; mt++) {
                uint32_t af[4];
                uint32_t o = (uint32_t)((wm * 64 + mt * 16) * 80 + ks * 32) + aOff;
                LDSM4(af, aB + o);
                #pragma unroll
                for (int nt = 0; nt < 4; nt++) {
                    int np = nt >> 1, sub = (nt & 1) * 2;
                    MMA_F16(acc[mt][nt], af, bf[np][sub], bf[np][sub + 1]);
                }
            }
        }
        st = (st + 1) & (STAGES - 1);
    }

    // --- epilogue ---
    #pragma unroll
    for (int mt = 0; mt < 4; mt++) {
        int r0 = bm + wm * 64 + mt * 16 + g;
        #pragma unroll
        for (int nt = 0; nt < 4; nt++) {
            int c = bn + wn * 32 + nt * 8 + t4 * 2;
            float v[4];
            v[0] = acc[mt][nt][0] + bias[c];
            v[1] = acc[mt][nt][1] + bias[c + 1];
            v[2] = acc[mt][nt][2] + bias[c];
            v[3] = acc[mt][nt][3] + bias[c + 1];
            if (gelu) {
                #pragma unroll
                for (int q = 0; q < 4; q++)
                    v[q] = 0.5f * v[q] * (1.0f + erff(v[q] * 0.70710678118654752f));
            }
            if (res) {
                v[0] += res[(size_t)r0 * N + c];
                v[1] += res[(size_t)r0 * N + c + 1];
                v[2] += res[(size_t)(r0 + 8) * N + c];
                v[3] += res[(size_t)(r0 + 8) * N + c + 1];
            }
            if (outF) {
                *(float2*)(outF + (size_t)r0 * N + c)       = make_float2(v[0], v[1]);
                *(float2*)(outF + (size_t)(r0 + 8) * N + c) = make_float2(v[2], v[3]);
            } else {
                *(uint32_t*)(outH + (size_t)r0 * N + c)       = pack2_h(v[0], v[1]);
                *(uint32_t*)(outH + (size_t)(r0 + 8) * N + c) = pack2_h(v[2], v[3]);
            }
        }
    }
}

// ---------------- flash attention, fp16, 3-stage single-barrier ----------------
#define ATILE 9216u
#define ASTAGES 3
#define ATT_SMEM (ASTAGES * 2 * 9216)

__global__ __launch_bounds__(128)
void attn_mma_kernel(const unsigned short* __restrict__ qkv,
                     unsigned short* __restrict__ O) {
    extern __shared__ char smem[];
    const uint32_t sb = smem_u32(smem);
    const int h  = blockIdx.y;
    const int q0 = blockIdx.x * 64;
    const int tid = threadIdx.x;
    const int w = tid >> 5, lane = tid & 31;
    const int g = lane >> 2, t4 = lane & 3;
    const int qcol = h * HDK, kcol = DIM + h * HDK, vcol = 2 * DIM + h * HDK;

    const uint32_t aOff = (uint32_t)((((lane >> 3) & 1) * 8 + (lane & 7)) * 144 + (lane >> 4) * 16);
    const uint32_t bOff = (uint32_t)(((lane >> 4) * 8 + (lane & 7)) * 144 + ((lane >> 3) & 1) * 16);
    const uint32_t vOff = (uint32_t)((lane & 15) * 144 + (lane >> 4) * 16);

    #define AK(s) (sb + (uint32_t)(s) * 2u * ATILE)
    #define AV(s) (AK(s) + ATILE)

    // stage Q through smem (stage 0 region) into registers
    #pragma unroll
    for (int u = 0; u < 4; u++) {
        int idx = tid + u * 128;
        int row = idx >> 3, c16 = idx & 7;
        cp_async16(AK(0) + (uint32_t)(row * 144 + c16 * 16),
                   qkv + (size_t)(q0 + row) * QKVN + qcol + c16 * 8);
    }
    CP_COMMIT(); CP_WAIT(0); __syncthreads();

    uint32_t qh[4][4];
    #pragma unroll
    for (int ks = 0; ks < 4; ks++) {
        uint32_t o = (uint32_t)(w * 16 * 144 + ks * 32);
        LDSM4(qh[ks], AK(0) + o + aOff);
    }
    __syncthreads();

    auto load_kv = [&](int st, int kt) {
        #pragma unroll
        for (int u = 0; u < 4; u++) {
            int idx = tid + u * 128;
            int row = idx >> 3, c16 = idx & 7;
            uint32_t off = (uint32_t)(row * 144 + c16 * 16);
            cp_async16(AK(st) + off, qkv + (size_t)(kt + row) * QKVN + kcol + c16 * 8);
            cp_async16(AV(st) + off, qkv + (size_t)(kt + row) * QKVN + vcol + c16 * 8);
        }
        CP_COMMIT();
    };
    load_kv(0, 0);
    load_kv(1, 64);

    float of[8][4];
    #pragma unroll
    for (int j = 0; j < 8; j++)
        #pragma unroll
        for (int q = 0; q < 4; q++) of[j][q] = 0.f;
    float m0 = -1e30f, m1 = -1e30f, l0 = 0.f, l1 = 0.f;

    const int NIT = SQ / 64;
    for (int it = 0; it < NIT; it++) {
        CP_WAIT(1);
        __syncthreads();
        if (it + 2 < NIT) load_kv((it + 2) % ASTAGES, (it + 2) * 64);
        else              CP_COMMIT();
        const int st = it % ASTAGES;

        float sf[8][4];
        #pragma unroll
        for (int j = 0; j < 8; j++)
            #pragma unroll
            for (int q = 0; q < 4; q++) sf[j][q] = 0.f;

        #pragma unroll
        for (int ks = 0; ks < 4; ks++) {
            #pragma unroll
            for (int nb = 0; nb < 4; nb++) {
                uint32_t kf[4];
                LDSM4(kf, AK(st) + (uint32_t)(nb * 16 * 144 + ks * 32) + bOff);
                MMA_F16(sf[2*nb],   qh[ks], kf[0], kf[1]);
                MMA_F16(sf[2*nb+1], qh[ks], kf[2], kf[3]);
            }
        }

        float mx0 = -1e30f, mx1 = -1e30f;
        #pragma unroll
        for (int j = 0; j < 8; j++) {
            #pragma unroll
            for (int q = 0; q < 4; q++) sf[j][q] *= 0.125f;
            mx0 = fmaxf(mx0, fmaxf(sf[j][0], sf[j][1]));
            mx1 = fmaxf(mx1, fmaxf(sf[j][2], sf[j][3]));
        }
        mx0 = fmaxf(mx0, __shfl_xor_sync(0xffffffffu, mx0, 1));
        mx0 = fmaxf(mx0, __shfl_xor_sync(0xffffffffu, mx0, 2));
        mx1 = fmaxf(mx1, __shfl_xor_sync(0xffffffffu, mx1, 1));
        mx1 = fmaxf(mx1, __shfl_xor_sync(0xffffffffu, mx1, 2));
        float mn0 = fmaxf(m0, mx0), mn1 = fmaxf(m1, mx1);
        float sc0 = __expf(m0 - mn0), sc1 = __expf(m1 - mn1);
        m0 = mn0; m1 = mn1;
        float s0 = 0.f, s1 = 0.f;
        #pragma unroll
        for (int j = 0; j < 8; j++) {
            sf[j][0] = __expf(sf[j][0] - mn0); s0 += sf[j][0];
            sf[j][1] = __expf(sf[j][1] - mn0); s0 += sf[j][1];
            sf[j][2] = __expf(sf[j][2] - mn1); s1 += sf[j][2];
            sf[j][3] = __expf(sf[j][3] - mn1); s1 += sf[j][3];
        }
        s0 += __shfl_xor_sync(0xffffffffu, s0, 1);
        s0 += __shfl_xor_sync(0xffffffffu, s0, 2);
        s1 += __shfl_xor_sync(0xffffffffu, s1, 1);
        s1 += __shfl_xor_sync(0xffffffffu, s1, 2);
        l0 = l0 * sc0 + s0;
        l1 = l1 * sc1 + s1;
        #pragma unroll
        for (int j = 0; j < 8; j++) {
            of[j][0] *= sc0; of[j][1] *= sc0;
            of[j][2] *= sc1; of[j][3] *= sc1;
        }

        #pragma unroll
        for (int jp = 0; jp < 4; jp++) {
            uint32_t p0 = pack2_h(sf[2*jp][0],   sf[2*jp][1]);
            uint32_t p1 = pack2_h(sf[2*jp][2],   sf[2*jp][3]);
            uint32_t p2 = pack2_h(sf[2*jp+1][0], sf[2*jp+1][1]);
            uint32_t p3 = pack2_h(sf[2*jp+1][2], sf[2*jp+1][3]);
            #pragma unroll
            for (int nb = 0; nb < 4; nb++) {
                uint32_t vf[4];
                LDSM4T(vf, AV(st) + (uint32_t)(jp * 16 * 144 + nb * 16 * 2) + vOff);
                MMA_F16R(of[2*nb],   p0, p1, p2, p3, vf[0], vf[1]);
                MMA_F16R(of[2*nb+1], p0, p1, p2, p3, vf[2], vf[3]);
            }
        }
    }

    float inv0 = 1.0f / l0, inv1 = 1.0f / l1;
    int r0 = q0 + w * 16 + g;
    #pragma unroll
    for (int j = 0; j < 8; j++) {
        int d = 8 * j + 2 * t4;
        *(uint32_t*)(O + (size_t)h * SQ * HDK + (size_t)r0 * HDK + d) =
            pack2_h(of[j][0] * inv0, of[j][1] * inv0);
        *(uint32_t*)(O + (size_t)h * SQ * HDK + (size_t)(r0 + 8) * HDK + d) =
            pack2_h(of[j][2] * inv1, of[j][3] * inv1);
    }
}

// ---------------- launch ----------------
extern "C" void kernel_launch(void* const* d_in, const int* in_sizes, int n_in,
                              void* d_out, int out_size) {
    const float* x     = (const float*)d_in[0];
    const float* wq    = (const float*)d_in[1];
    const float* bq    = (const float*)d_in[2];
    const float* wk    = (const float*)d_in[3];
    const float* bk    = (const float*)d_in[4];
    const float* wv    = (const float*)d_in[5];
    const float* bv    = (const float*)d_in[6];
    const float* wo    = (const float*)d_in[7];
    const float* bo    = (const float*)d_in[8];
    const float* w1    = (const float*)d_in[9];
    const float* b1    = (const float*)d_in[10];
    const float* w2    = (const float*)d_in[11];
    const float* b2    = (const float*)d_in[12];
    const float* ln1_g = (const float*)d_in[13];
    const float* ln1_b = (const float*)d_in[14];
    const float* ln2_g = (const float*)d_in[15];
    const float* ln2_b = (const float*)d_in[16];
    float* out = (float*)d_out;

    unsigned short *hh, *qkv, *ao, *f, *wqkvh, *woh, *w1h, *w2h;
    float *x1, *bqkv;
    cudaGetSymbolAddress((void**)&hh,   g_h);
    cudaGetSymbolAddress((void**)&qkv,  g_qkv);
    cudaGetSymbolAddress((void**)&ao,   g_ao);
    cudaGetSymbolAddress((void**)&x1,   g_x1);
    cudaGetSymbolAddress((void**)&f,    g_f);
    cudaGetSymbolAddress((void**)&wqkvh, g_wqkv);
    cudaGetSymbolAddress((void**)&woh,  g_wo);
    cudaGetSymbolAddress((void**)&w1h,  g_w1);
    cudaGetSymbolAddress((void**)&w2h,  g_w2);
    cudaGetSymbolAddress((void**)&bqkv, g_bqkv);

    cudaFuncSetAttribute(gemm_mma_kernel,
                         cudaFuncAttributeMaxDynamicSharedMemorySize, GEMM_SMEM);
    cudaFuncSetAttribute(attn_mma_kernel,
                         cudaFuncAttributeMaxDynamicSharedMemorySize, ATT_SMEM);

    // prep: LN1 + all weight conversion in 2 launches
    ln_h_kernel<<<SQ, 256>>>(x, ln1_g, ln1_b, hh);
    prep_kernel<<<12300, dim3(32, 8)>>>(wq, wk, wv, wo, w1, w2, bq, bk, bv,
                                        wqkvh, woh, w1h, w2h, bqkv);
    // QKV fused GEMM -> fp16
    gemm_mma_kernel<<<dim3(QKVN/128, SQ/128), 256, GEMM_SMEM>>>(
        hh, wqkvh, bqkv, nullptr, nullptr, qkv, QKVN, DIM, 0);
    // attention -> ao fp16
    attn_mma_kernel<<<dim3(SQ/64, NH), 128, ATT_SMEM>>>(qkv, ao);
    // O-proj + residual(x) -> x1 fp32
    gemm_mma_kernel<<<dim3(DIM/128, SQ/128), 256, GEMM_SMEM>>>(
        ao, woh, bo, x, x1, nullptr, DIM, DIM, 0);
    // LN2 -> fp16
    ln_h_kernel<<<SQ, 256>>>(x1, ln2_g, ln2_b, hh);
    // FFN1 + GELU -> f fp16
    gemm_mma_kernel<<<dim3(MLPD/128, SQ/128), 256, GEMM_SMEM>>>(
        hh, w1h, b1, nullptr, nullptr, f, MLPD, DIM, 1);
    // FFN2 + residual(x1) -> out fp32
    gemm_mma_kernel<<<dim3(DIM/128, SQ/128), 256, GEMM_SMEM>>>(
        f, w2h, b2, x1, out, nullptr, DIM, MLPD, 0);
}

// round 9
// speedup vs baseline: 1.4947x; 1.4947x over previous
#include <cuda_runtime.h>
#include <cuda_fp16.h>
#include <math.h>
#include <stdint.h>

#define SQ   2048
#define DIM  1024
#define NH   16
#define HDK  64
#define MLPD 4096
#define QKVN 3072

// ---------------- scratch (no allocations allowed) ----------------
__device__ unsigned short g_h   [SQ*DIM];     // fp16 LN out
__device__ unsigned short g_qkv [SQ*QKVN];    // fp16 q,k,v
__device__ unsigned short g_ao  [SQ*DIM];     // fp16 attention out [H,S,DK]
__device__ float          g_x1  [SQ*DIM];
__device__ unsigned short g_f   [SQ*MLPD];    // fp16 gelu out
__device__ unsigned short g_wqkv[QKVN*DIM];   // fp16 weights, [N,K]
__device__ unsigned short g_wo  [DIM*DIM];
__device__ unsigned short g_w1  [MLPD*DIM];
__device__ unsigned short g_w2  [DIM*MLPD];
__device__ float          g_bqkv[QKVN];

// ---------------- helpers ----------------
__device__ __forceinline__ uint32_t smem_u32(const void* p) {
    uint32_t a;
    asm("{ .reg .u64 t; cvta.to.shared.u64 t, %1; cvt.u32.u64 %0, t; }" : "=r"(a) : "l"(p));
    return a;
}

__device__ __forceinline__ void cp_async16(uint32_t sdst, const void* gsrc) {
    asm volatile("cp.async.cg.shared.global [%0], [%1], 16;" :: "r"(sdst), "l"(gsrc) : "memory");
}
#define CP_COMMIT() asm volatile("cp.async.commit_group;" ::: "memory")
#define CP_WAIT(n)  asm volatile("cp.async.wait_group %0;" :: "n"(n) : "memory")

#define LDSM4(r, addr) \
    asm volatile("ldmatrix.sync.aligned.m8n8.x4.shared.b16 {%0,%1,%2,%3}, [%4];" \
        : "=r"((r)[0]), "=r"((r)[1]), "=r"((r)[2]), "=r"((r)[3]) : "r"(addr))

#define LDSM4T(r, addr) \
    asm volatile("ldmatrix.sync.aligned.m8n8.x4.trans.shared.b16 {%0,%1,%2,%3}, [%4];" \
        : "=r"((r)[0]), "=r"((r)[1]), "=r"((r)[2]), "=r"((r)[3]) : "r"(addr))

#define MMA_F16(c, a, b0, b1) \
    asm volatile("mma.sync.aligned.m16n8k16.row.col.f32.f16.f16.f32 " \
        "{%0,%1,%2,%3}, {%4,%5,%6,%7}, {%8,%9}, {%0,%1,%2,%3};" \
        : "+f"((c)[0]), "+f"((c)[1]), "+f"((c)[2]), "+f"((c)[3]) \
        : "r"((a)[0]), "r"((a)[1]), "r"((a)[2]), "r"((a)[3]), "r"(b0), "r"(b1))

#define MMA_F16R(c, a0, a1, a2, a3, b0, b1) \
    asm volatile("mma.sync.aligned.m16n8k16.row.col.f32.f16.f16.f32 " \
        "{%0,%1,%2,%3}, {%4,%5,%6,%7}, {%8,%9}, {%0,%1,%2,%3};" \
        : "+f"((c)[0]), "+f"((c)[1]), "+f"((c)[2]), "+f"((c)[3]) \
        : "r"(a0), "r"(a1), "r"(a2), "r"(a3), "r"(b0), "r"(b1))

__device__ __forceinline__ unsigned short f2h(float v) {
    return __half_as_ushort(__float2half_rn(v));
}
__device__ __forceinline__ uint32_t pack2_h(float a, float b) {
    __half2 h = __floats2half2_rn(a, b);
    return *(uint32_t*)&h;
}

// ---------------- layernorm -> fp16 ----------------
__device__ __forceinline__ float block_sum_256(float v, float* sh) {
    int lane = threadIdx.x & 31, w = threadIdx.x >> 5;
    #pragma unroll
    for (int o = 16; o; o >>= 1) v += __shfl_xor_sync(0xffffffffu, v, o);
    __syncthreads();
    if (lane == 0) sh[w] = v;
    __syncthreads();
    float r = 0.f;
    #pragma unroll
    for (int i = 0; i < 8; i++) r += sh[i];
    return r;
}

__global__ void ln_h_kernel(const float* __restrict__ x, const float* __restrict__ g,
                            const float* __restrict__ b, unsigned short* __restrict__ oh) {
    __shared__ float sh[8];
    int row = blockIdx.x;
    const float* xr = x + (size_t)row * DIM;
    int t = threadIdx.x;
    float v0[4];
    float s = 0.f;
    #pragma unroll
    for (int u = 0; u < 4; u++) { v0[u] = xr[t + u * 256]; s += v0[u]; }
    s = block_sum_256(s, sh);
    float mean = s * (1.0f / DIM);
    float vs = 0.f;
    #pragma unroll
    for (int u = 0; u < 4; u++) { float d = v0[u] - mean; vs += d * d; }
    vs = block_sum_256(vs, sh);
    float rstd = rsqrtf(vs * (1.0f / DIM) + 1e-5f);
    #pragma unroll
    for (int u = 0; u < 4; u++) {
        int c = t + u * 256;
        oh[(size_t)row * DIM + c] = f2h((v0[u] - mean) * rstd * g[c] + b[c]);
    }
}

// ---------------- merged weight prep: all transposes + bias concat ----------------
// blocks [0,1024) wq | [1024,2048) wk | [2048,3072) wv | [3072,4096) wo
// [4096,8192) w1 | [8192,12288) w2 | [12288,12300) bias
__global__ void prep_kernel(const float* __restrict__ wq, const float* __restrict__ wk,
                            const float* __restrict__ wv, const float* __restrict__ wo,
                            const float* __restrict__ w1, const float* __restrict__ w2,
                            const float* __restrict__ bq, const float* __restrict__ bk,
                            const float* __restrict__ bv,
                            unsigned short* __restrict__ owqkv, unsigned short* __restrict__ owo,
                            unsigned short* __restrict__ ow1, unsigned short* __restrict__ ow2,
                            float* __restrict__ obqkv) {
    int bid = blockIdx.x;
    if (bid >= 12288) {
        int i = (bid - 12288) * 256 + threadIdx.y * 32 + threadIdx.x;
        if (i < DIM) obqkv[i] = bq[i];
        else if (i < 2 * DIM) obqkv[i] = bk[i - DIM];
        else obqkv[i] = bv[i - 2 * DIM];
        return;
    }
    const float* in;
    unsigned short* out;
    int R, C, l;
    if (bid < 4096) {
        l = bid & 1023;
        R = DIM; C = DIM;
        int m = bid >> 10;
        in  = (m == 0) ? wq : (m == 1) ? wk : (m == 2) ? wv : wo;
        out = (m == 3) ? owo : owqkv + (size_t)m * DIM * DIM;
    } else if (bid < 8192) {
        l = bid - 4096; R = DIM; C = MLPD; in = w1; out = ow1;
    } else {
        l = bid - 8192; R = MLPD; C = DIM; in = w2; out = ow2;
    }
    int nbx = C >> 5;
    int bx = l % nbx, by = l / nbx;
    __shared__ float t[32][33];
    int c0 = bx * 32, r0 = by * 32;
    #pragma unroll
    for (int u = 0; u < 4; u++) {
        int r = r0 + threadIdx.y + u * 8;
        t[threadIdx.y + u * 8][threadIdx.x] = in[(size_t)r * C + c0 + threadIdx.x];
    }
    __syncthreads();
    #pragma unroll
    for (int u = 0; u < 4; u++) {
        int c = c0 + threadIdx.y + u * 8;
        out[(size_t)c * R + r0 + threadIdx.x] = f2h(t[threadIdx.x][threadIdx.y + u * 8]);
    }
}

// ---------------- fp16 GEMM: C = A_f16 @ B_f16^T (R7 double-barrier) ----------------
#define TILEB 10240u
#define STAGES 4
#define GEMM_SMEM (STAGES * 2 * 10240)

__global__ __launch_bounds__(256, 2)
void gemm_mma_kernel(const unsigned short* __restrict__ A, const unsigned short* __restrict__ B,
                     const float* __restrict__ bias, const float* __restrict__ res,
                     float* __restrict__ outF, unsigned short* __restrict__ outH,
                     int N, int K, int gelu) {
    extern __shared__ char smem[];
    const uint32_t sb = smem_u32(smem);
    const int tid  = threadIdx.x;
    const int wid  = tid >> 5;
    const int lane = tid & 31;
    const int wm = wid >> 2;
    const int wn = wid & 3;
    const int bm = blockIdx.y * 128;
    const int bn = blockIdx.x * 128;
    const int g  = lane >> 2;
    const int t4 = lane & 3;

    const uint32_t aOff = (uint32_t)((((lane >> 3) & 1) * 8 + (lane & 7)) * 80 + (lane >> 4) * 16);
    const uint32_t bOff = (uint32_t)(((lane >> 4) * 8 + (lane & 7)) * 80 + ((lane >> 3) & 1) * 16);

    float acc[4][4][4];
    #pragma unroll
    for (int i = 0; i < 4; i++)
        #pragma unroll
        for (int j = 0; j < 4; j++)
            #pragma unroll
            for (int q = 0; q < 4; q++) acc[i][j][q] = 0.f;

    const int NCH = K >> 5;
    const unsigned short* gsrc[2] = {A, B};
    const int rbase[2] = {bm, bn};

    auto load_chunk = [&](int stage, int k0) {
        #pragma unroll
        for (int t = 0; t < 2; t++) {
            uint32_t dst = sb + (uint32_t)(stage * 2 + t) * TILEB;
            const unsigned short* gp = gsrc[t];
            #pragma unroll
            for (int u = 0; u < 2; u++) {
                int idx = tid + 256 * u;
                int r = idx >> 2;
                int cc = idx & 3;
                cp_async16(dst + (uint32_t)(r * 80 + cc * 16),
                           gp + (size_t)(rbase[t] + r) * K + k0 + cc * 8);
            }
        }
        CP_COMMIT();
    };

    #pragma unroll
    for (int s = 0; s < STAGES; s++) load_chunk(s, s * 32);

    int st = 0;
    for (int i = 0; i < NCH; i++) {
        CP_WAIT(STAGES - 1);
        __syncthreads();

        const uint32_t aB = sb + (uint32_t)(st * 2) * TILEB;
        const uint32_t bB = aB + TILEB;

        #pragma unroll
        for (int ks = 0; ks < 2; ks++) {
            uint32_t bf[2][4];
            #pragma unroll
            for (int np = 0; np < 2; np++) {
                uint32_t o = (uint32_t)((wn * 32 + np * 16) * 80 + ks * 32) + bOff;
                LDSM4(bf[np], bB + o);
            }
            #pragma unroll
            for (int mt = 0; mt < 4; mt++) {
                uint32_t af[4];
                uint32_t o = (uint32_t)((wm * 64 + mt * 16) * 80 + ks * 32) + aOff;
                LDSM4(af, aB + o);
                #pragma unroll
                for (int nt = 0; nt < 4; nt++) {
                    int np = nt >> 1, sub = (nt & 1) * 2;
                    MMA_F16(acc[mt][nt], af, bf[np][sub], bf[np][sub + 1]);
                }
            }
        }
        __syncthreads();

        if (i + STAGES < NCH) load_chunk(st, (i + STAGES) * 32);
        else                  CP_COMMIT();
        st = (st + 1) & (STAGES - 1);
    }

    // --- epilogue ---
    #pragma unroll
    for (int mt = 0; mt < 4; mt++) {
        int r0 = bm + wm * 64 + mt * 16 + g;
        #pragma unroll
        for (int nt = 0; nt < 4; nt++) {
            int c = bn + wn * 32 + nt * 8 + t4 * 2;
            float v[4];
            v[0] = acc[mt][nt][0] + bias[c];
            v[1] = acc[mt][nt][1] + bias[c + 1];
            v[2] = acc[mt][nt][2] + bias[c];
            v[3] = acc[mt][nt][3] + bias[c + 1];
            if (gelu) {
                #pragma unroll
                for (int q = 0; q < 4; q++)
                    v[q] = 0.5f * v[q] * (1.0f + erff(v[q] * 0.70710678118654752f));
            }
            if (res) {
                v[0] += res[(size_t)r0 * N + c];
                v[1] += res[(size_t)r0 * N + c + 1];
                v[2] += res[(size_t)(r0 + 8) * N + c];
                v[3] += res[(size_t)(r0 + 8) * N + c + 1];
            }
            if (outF) {
                *(float2*)(outF + (size_t)r0 * N + c)       = make_float2(v[0], v[1]);
                *(float2*)(outF + (size_t)(r0 + 8) * N + c) = make_float2(v[2], v[3]);
            } else {
                *(uint32_t*)(outH + (size_t)r0 * N + c)       = pack2_h(v[0], v[1]);
                *(uint32_t*)(outH + (size_t)(r0 + 8) * N + c) = pack2_h(v[2], v[3]);
            }
        }
    }
}

// ---------------- flash attention, fp16 (R7 2-stage double-barrier) ----------------
#define ATILE 9216u
#define ATT_SMEM (2 * 2 * 9216)

__global__ __launch_bounds__(128)
void attn_mma_kernel(const unsigned short* __restrict__ qkv,
                     unsigned short* __restrict__ O) {
    extern __shared__ char smem[];
    const uint32_t sb = smem_u32(smem);
    const int h  = blockIdx.y;
    const int q0 = blockIdx.x * 64;
    const int tid = threadIdx.x;
    const int w = tid >> 5, lane = tid & 31;
    const int g = lane >> 2, t4 = lane & 3;
    const int qcol = h * HDK, kcol = DIM + h * HDK, vcol = 2 * DIM + h * HDK;

    const uint32_t aOff = (uint32_t)((((lane >> 3) & 1) * 8 + (lane & 7)) * 144 + (lane >> 4) * 16);
    const uint32_t bOff = (uint32_t)(((lane >> 4) * 8 + (lane & 7)) * 144 + ((lane >> 3) & 1) * 16);
    const uint32_t vOff = (uint32_t)((lane & 15) * 144 + (lane >> 4) * 16);

    #define AK(s) (sb + (uint32_t)(s) * 2u * ATILE)
    #define AV(s) (AK(s) + ATILE)

    // stage Q through smem into registers
    #pragma unroll
    for (int u = 0; u < 4; u++) {
        int idx = tid + u * 128;
        int row = idx >> 3, c16 = idx & 7;
        cp_async16(AK(0) + (uint32_t)(row * 144 + c16 * 16),
                   qkv + (size_t)(q0 + row) * QKVN + qcol + c16 * 8);
    }
    CP_COMMIT(); CP_WAIT(0); __syncthreads();

    uint32_t qh[4][4];
    #pragma unroll
    for (int ks = 0; ks < 4; ks++) {
        uint32_t o = (uint32_t)(w * 16 * 144 + ks * 32);
        LDSM4(qh[ks], AK(0) + o + aOff);
    }
    __syncthreads();

    auto load_kv = [&](int st, int kt) {
        #pragma unroll
        for (int u = 0; u < 4; u++) {
            int idx = tid + u * 128;
            int row = idx >> 3, c16 = idx & 7;
            uint32_t off = (uint32_t)(row * 144 + c16 * 16);
            cp_async16(AK(st) + off, qkv + (size_t)(kt + row) * QKVN + kcol + c16 * 8);
            cp_async16(AV(st) + off, qkv + (size_t)(kt + row) * QKVN + vcol + c16 * 8);
        }
        CP_COMMIT();
    };
    load_kv(0, 0);
    load_kv(1, 64);

    float of[8][4];
    #pragma unroll
    for (int j = 0; j < 8; j++)
        #pragma unroll
        for (int q = 0; q < 4; q++) of[j][q] = 0.f;
    float m0 = -1e30f, m1 = -1e30f, l0 = 0.f, l1 = 0.f;

    for (int it = 0; it < SQ / 64; it++) {
        CP_WAIT(1);
        __syncthreads();
        const int st = it & 1;

        float sf[8][4];
        #pragma unroll
        for (int j = 0; j < 8; j++)
            #pragma unroll
            for (int q = 0; q < 4; q++) sf[j][q] = 0.f;

        #pragma unroll
        for (int ks = 0; ks < 4; ks++) {
            #pragma unroll
            for (int nb = 0; nb < 4; nb++) {
                uint32_t kf[4];
                LDSM4(kf, AK(st) + (uint32_t)(nb * 16 * 144 + ks * 32) + bOff);
                MMA_F16(sf[2*nb],   qh[ks], kf[0], kf[1]);
                MMA_F16(sf[2*nb+1], qh[ks], kf[2], kf[3]);
            }
        }

        float mx0 = -1e30f, mx1 = -1e30f;
        #pragma unroll
        for (int j = 0; j < 8; j++) {
            #pragma unroll
            for (int q = 0; q < 4; q++) sf[j][q] *= 0.125f;
            mx0 = fmaxf(mx0, fmaxf(sf[j][0], sf[j][1]));
            mx1 = fmaxf(mx1, fmaxf(sf[j][2], sf[j][3]));
        }
        mx0 = fmaxf(mx0, __shfl_xor_sync(0xffffffffu, mx0, 1));
        mx0 = fmaxf(mx0, __shfl_xor_sync(0xffffffffu, mx0, 2));
        mx1 = fmaxf(mx1, __shfl_xor_sync(0xffffffffu, mx1, 1));
        mx1 = fmaxf(mx1, __shfl_xor_sync(0xffffffffu, mx1, 2));
        float mn0 = fmaxf(m0, mx0), mn1 = fmaxf(m1, mx1);
        float sc0 = __expf(m0 - mn0), sc1 = __expf(m1 - mn1);
        m0 = mn0; m1 = mn1;
        float s0 = 0.f, s1 = 0.f;
        #pragma unroll
        for (int j = 0; j < 8; j++) {
            sf[j][0] = __expf(sf[j][0] - mn0); s0 += sf[j][0];
            sf[j][1] = __expf(sf[j][1] - mn0); s0 += sf[j][1];
            sf[j][2] = __expf(sf[j][2] - mn1); s1 += sf[j][2];
            sf[j][3] = __expf(sf[j][3] - mn1); s1 += sf[j][3];
        }
        s0 += __shfl_xor_sync(0xffffffffu, s0, 1);
        s0 += __shfl_xor_sync(0xffffffffu, s0, 2);
        s1 += __shfl_xor_sync(0xffffffffu, s1, 1);
        s1 += __shfl_xor_sync(0xffffffffu, s1, 2);
        l0 = l0 * sc0 + s0;
        l1 = l1 * sc1 + s1;
        #pragma unroll
        for (int j = 0; j < 8; j++) {
            of[j][0] *= sc0; of[j][1] *= sc0;
            of[j][2] *= sc1; of[j][3] *= sc1;
        }

        #pragma unroll
        for (int jp = 0; jp < 4; jp++) {
            uint32_t p0 = pack2_h(sf[2*jp][0],   sf[2*jp][1]);
            uint32_t p1 = pack2_h(sf[2*jp][2],   sf[2*jp][3]);
            uint32_t p2 = pack2_h(sf[2*jp+1][0], sf[2*jp+1][1]);
            uint32_t p3 = pack2_h(sf[2*jp+1][2], sf[2*jp+1][3]);
            #pragma unroll
            for (int nb = 0; nb < 4; nb++) {
                uint32_t vf[4];
                LDSM4T(vf, AV(st) + (uint32_t)(jp * 16 * 144 + nb * 16 * 2) + vOff);
                MMA_F16R(of[2*nb],   p0, p1, p2, p3, vf[0], vf[1]);
                MMA_F16R(of[2*nb+1], p0, p1, p2, p3, vf[2], vf[3]);
            }
        }

        __syncthreads();
        if (it + 2 < SQ / 64) load_kv(st, (it + 2) * 64);
        else                  CP_COMMIT();
    }

    float inv0 = 1.0f / l0, inv1 = 1.0f / l1;
    int r0 = q0 + w * 16 + g;
    #pragma unroll
    for (int j = 0; j < 8; j++) {
        int d = 8 * j + 2 * t4;
        *(uint32_t*)(O + (size_t)h * SQ * HDK + (size_t)r0 * HDK + d) =
            pack2_h(of[j][0] * inv0, of[j][1] * inv0);
        *(uint32_t*)(O + (size_t)h * SQ * HDK + (size_t)(r0 + 8) * HDK + d) =
            pack2_h(of[j][2] * inv1, of[j][3] * inv1);
    }
}

// ---------------- launch ----------------
extern "C" void kernel_launch(void* const* d_in, const int* in_sizes, int n_in,
                              void* d_out, int out_size) {
    const float* x     = (const float*)d_in[0];
    const float* wq    = (const float*)d_in[1];
    const float* bq    = (const float*)d_in[2];
    const float* wk    = (const float*)d_in[3];
    const float* bk    = (const float*)d_in[4];
    const float* wv    = (const float*)d_in[5];
    const float* bv    = (const float*)d_in[6];
    const float* wo    = (const float*)d_in[7];
    const float* bo    = (const float*)d_in[8];
    const float* w1    = (const float*)d_in[9];
    const float* b1    = (const float*)d_in[10];
    const float* w2    = (const float*)d_in[11];
    const float* b2    = (const float*)d_in[12];
    const float* ln1_g = (const float*)d_in[13];
    const float* ln1_b = (const float*)d_in[14];
    const float* ln2_g = (const float*)d_in[15];
    const float* ln2_b = (const float*)d_in[16];
    float* out = (float*)d_out;

    unsigned short *hh, *qkv, *ao, *f, *wqkvh, *woh, *w1h, *w2h;
    float *x1, *bqkv;
    cudaGetSymbolAddress((void**)&hh,   g_h);
    cudaGetSymbolAddress((void**)&qkv,  g_qkv);
    cudaGetSymbolAddress((void**)&ao,   g_ao);
    cudaGetSymbolAddress((void**)&x1,   g_x1);
    cudaGetSymbolAddress((void**)&f,    g_f);
    cudaGetSymbolAddress((void**)&wqkvh, g_wqkv);
    cudaGetSymbolAddress((void**)&woh,  g_wo);
    cudaGetSymbolAddress((void**)&w1h,  g_w1);
    cudaGetSymbolAddress((void**)&w2h,  g_w2);
    cudaGetSymbolAddress((void**)&bqkv, g_bqkv);

    cudaFuncSetAttribute(gemm_mma_kernel,
                         cudaFuncAttributeMaxDynamicSharedMemorySize, GEMM_SMEM);
    cudaFuncSetAttribute(attn_mma_kernel,
                         cudaFuncAttributeMaxDynamicSharedMemorySize, ATT_SMEM);

    // prep: LN1 + all weight conversion in 2 launches
    ln_h_kernel<<<SQ, 256>>>(x, ln1_g, ln1_b, hh);
    prep_kernel<<<12300, dim3(32, 8)>>>(wq, wk, wv, wo, w1, w2, bq, bk, bv,
                                        wqkvh, woh, w1h, w2h, bqkv);
    // QKV fused GEMM -> fp16
    gemm_mma_kernel<<<dim3(QKVN/128, SQ/128), 256, GEMM_SMEM>>>(
        hh, wqkvh, bqkv, nullptr, nullptr, qkv, QKVN, DIM, 0);
    // attention -> ao fp16
    attn_mma_kernel<<<dim3(SQ/64, NH), 128, ATT_SMEM>>>(qkv, ao);
    // O-proj + residual(x) -> x1 fp32
    gemm_mma_kernel<<<dim3(DIM/128, SQ/128), 256, GEMM_SMEM>>>(
        ao, woh, bo, x, x1, nullptr, DIM, DIM, 0);
    // LN2 -> fp16
    ln_h_kernel<<<SQ, 256>>>(x1, ln2_g, ln2_b, hh);
    // FFN1 + GELU -> f fp16
    gemm_mma_kernel<<<dim3(MLPD/128, SQ/128), 256, GEMM_SMEM>>>(
        hh, w1h, b1, nullptr, nullptr, f, MLPD, DIM, 1);
    // FFN2 + residual(x1) -> out fp32
    gemm_mma_kernel<<<dim3(DIM/128, SQ/128), 256, GEMM_SMEM>>>(
        f, w2h, b2, x1, out, nullptr, DIM, MLPD, 0);
}